// round 7
// baseline (speedup 1.0000x reference)
#include <cuda_runtime.h>
#include <math.h>

// Petrosian fractal features, 5 scales, T=4096, 57 windows/row.
// One WARP per row; 8 rows per 256-thread CTA; zero shared memory, zero
// __syncthreads. Row processed as 32 chunks of 128 elems (1 chunk = 1 prefix
// segment). Per chunk: 1 LDG.128/lane (4-deep prefetch pipeline), halo via
// shfl_down, segment sum via __reduce_add_sync kept in lane c's register.
// Chunk-boundary indicators resolved one chunk later from carried scalars.
// Windows: zc([128a,128b)) = S[b] - S[a] - (s[128b-2]+s[128b-1]).

#define T_LEN 4096
#define N_WIN 57
#define WARPS 8
#define FULL  0xffffffffu

__global__ __launch_bounds__(256)
void petrosian_kernel(const float* __restrict__ x, float* __restrict__ out, int n_rows) {
    const int lane = threadIdx.x & 31;
    const int wid  = threadIdx.x >> 5;
    const int row  = blockIdx.x * WARPS + wid;
    if (row >= n_rows) return;

    // chunk c: this lane's float4 lives at p4[c*32]
    const float4* p4 = (const float4*)(x + (size_t)row * T_LEN) + lane;

    float4 buf[4];
    #pragma unroll
    for (int i = 0; i < 4; i++) buf[i] = p4[i * 32];

    int   segreg = 0;          // lane c will hold full segment-c sum
    int   bcreg  = 0;          // lane m-1 holds bcorr[m] = s[128m-2]+s[128m-1]
    float cx127  = 0.0f;       // carried x[128c-1]
    float cd126  = 0.0f;       // carried d[128c-2]
    int   partial_prev = 0;    // chunk c-1 sum minus its 2 boundary indicators

    #pragma unroll 4
    for (int c = 0; c < 32; c++) {
        float4 v = buf[c & 3];
        if (c < 28) buf[c & 3] = p4[(c + 4) * 32];   // prefetch chunk c+4

        // halo from lane+1 (lane 31's copies unused: masked below)
        float h0 = __shfl_down_sync(FULL, v.x, 1);
        float h1 = __shfl_down_sync(FULL, v.y, 1);
        // broadcasts of this chunk's first two elements (for deferred boundary)
        float bx0 = __shfl_sync(FULL, v.x, 0);
        float bx1 = __shfl_sync(FULL, v.y, 0);

        // deferred boundary between chunk c-1 and c:
        //   s[128c-2] uses (cd126, d127); s[128c-1] uses (d127, d128)
        {
            float d127 = bx0 - cx127;
            float d128 = bx1 - bx0;
            int t = ((cd126 * d127 < 0.0f) ? 1 : 0) + ((d127 * d128 < 0.0f) ? 1 : 0);
            if (lane == c - 1) { segreg = partial_prev + t; bcreg = t; } // no-op when c==0
        }

        // in-chunk indicators: j = 128c + 4*lane + {0,1,2,3}
        float d0 = v.y - v.x, d1 = v.z - v.y, d2 = v.w - v.z;
        float d3 = h0 - v.w,  d4 = h1 - h0;
        int cnt = ((d0 * d1 < 0.0f) ? 1 : 0) + ((d1 * d2 < 0.0f) ? 1 : 0);
        if (lane < 31) cnt += ((d2 * d3 < 0.0f) ? 1 : 0) + ((d3 * d4 < 0.0f) ? 1 : 0);
        partial_prev = __reduce_add_sync(FULL, cnt);

        // carries for next chunk's boundary fixup
        cx127 = __shfl_sync(FULL, v.w, 31);
        cd126 = __shfl_sync(FULL, d2, 31);
    }
    // last chunk: s[4094], s[4095] invalid -> t = 0
    if (lane == 31) { segreg = partial_prev; bcreg = 0; }

    // inclusive scan over lanes: sc at lane l = S[l+1]
    int sc = segreg;
    #pragma unroll
    for (int off = 1; off < 32; off <<= 1) {
        int n = __shfl_up_sync(FULL, sc, off);
        if (lane >= off) sc += n;
    }

    // 57 outputs, 2 per lane
    const size_t obase = (size_t)row * N_WIN;
    #pragma unroll
    for (int half = 0; half < 2; half++) {
        int k  = lane + half * 32;
        int kk = (k < N_WIN) ? k : 0;
        int w, a; float L;
        if      (kk < 1)  { w = 4096; a = 0;             L = 3.612359948f; }
        else if (kk < 4)  { w = 2048; a = (kk - 1) * 8;  L = 3.311329954f; }
        else if (kk < 11) { w = 1024; a = (kk - 4) * 4;  L = 3.010299957f; }
        else if (kk < 26) { w = 512;  a = (kk - 11) * 2; L = 2.709269961f; }
        else              { w = 256;  a = kk - 26;       L = 2.408239965f; }
        int b = a + (w >> 7);

        int Sb = __shfl_sync(FULL, sc, b - 1);
        int Sa = __shfl_sync(FULL, sc, (a > 0) ? (a - 1) : 0);
        if (a == 0) Sa = 0;
        int bc = __shfl_sync(FULL, bcreg, b - 1);

        if (k < N_WIN) {
            float zc = (float)(Sb - Sa - bc);
            float wf = (float)w;
            float denom = L + log10f(wf / (wf + 0.4f * zc));
            out[obase + k] = L / denom;
        }
    }
}

extern "C" void kernel_launch(void* const* d_in, const int* in_sizes, int n_in,
                              void* d_out, int out_size) {
    const float* x = (const float*)d_in[0];
    float* out = (float*)d_out;
    int n_rows = in_sizes[0] / T_LEN;               // B*C = 4096
    int n_blocks = (n_rows + WARPS - 1) / WARPS;    // 512
    petrosian_kernel<<<n_blocks, 256>>>(x, out, n_rows);
}

// round 8
// speedup vs baseline: 1.1830x; 1.1830x over previous
#include <cuda_runtime.h>
#include <math.h>

// Petrosian fractal features, 5 scales, T=4096, 57 windows/row.
// One WARP per row, 8 rows/CTA, no smem, no __syncthreads.
// Row = 16 chunks of 256 elems (2 x 128-elem prefix segments per chunk).
// Each lane owns 2 float4: v0 = elems 4l..4l+3 (low half), v1 = 128+4l..+3
// (high half). Circular shfl (lane+1 mod 32) provides:
//   lanes 0-30: halo for their group;  lane 31: (from v1-shfl) lane0's v1 =
//   mid-boundary halo, and (from next iter's v0-shfl) next chunk's x0,x1 =
//   deferred end-boundary data. Segment sums via one packed redux
//   (low | high<<16). Windows: zc([128a,128b)) = S[b]-S[a]-bcorr[b].

#define T_LEN 4096
#define N_WIN 57
#define WARPS 8
#define FULL  0xffffffffu

__global__ __launch_bounds__(256)
void petrosian_kernel(const float* __restrict__ x, float* __restrict__ out, int n_rows) {
    const int lane = threadIdx.x & 31;
    const int wid  = threadIdx.x >> 5;
    const int row  = blockIdx.x * WARPS + wid;
    if (row >= n_rows) return;

    const float4* p4 = (const float4*)(x + (size_t)row * T_LEN);

    // 2-chunk prefetch pipeline (4 LDG.128 in flight)
    float4 b0[2], b1[2];
    #pragma unroll
    for (int i = 0; i < 2; i++) {
        b0[i] = p4[64 * i + lane];
        b1[i] = p4[64 * i + 32 + lane];
    }

    int   segreg = 0, bcreg = 0;   // lane m: segment-m sum / bcorr[m+1]
    int   prevHigh = 0;            // high-half sum of previous chunk (uniform)
    float cx = 0.0f, cd = 0.0f;    // lane 31 carries: x[255], d[254] of prev chunk
    const int nl = (lane + 1) & 31;

    #pragma unroll
    for (int c = 0; c < 16; c++) {
        float4 v0 = b0[c & 1], v1 = b1[c & 1];
        if (c < 14) {
            b0[c & 1] = p4[64 * (c + 2) + lane];
            b1[c & 1] = p4[64 * (c + 2) + 32 + lane];
        }

        float h0x = __shfl_sync(FULL, v0.x, nl);
        float h0y = __shfl_sync(FULL, v0.y, nl);
        float h1x = __shfl_sync(FULL, v1.x, nl);
        float h1y = __shfl_sync(FULL, v1.y, nl);

        // ---- deferred end-boundary of previous chunk: s[256c-2], s[256c-1]
        //      (lane 31 holds carries; h0x,h0y give it x[256c], x[256c+1])
        if (c > 0) {
            float dA = h0x - cx;        // d[256c-1]
            float dB = h0y - h0x;       // d[256c]
            int te = ((cd * dA < 0.0f) ? 1 : 0) + ((dA * dB < 0.0f) ? 1 : 0);
            te = __shfl_sync(FULL, te, 31);
            if (lane == 2 * c - 1) { segreg = prevHigh + te; bcreg = te; }
        }

        // ---- low half: j = 256c + 4l + {0..3}; lane31 halo = lane0's v1
        float fhx = (lane < 31) ? h0x : h1x;
        float fhy = (lane < 31) ? h0y : h1y;
        float d0 = v0.y - v0.x, d1 = v0.z - v0.y, d2 = v0.w - v0.z;
        float d3 = fhx - v0.w,  d4 = fhy - fhx;
        int sl2 = (d2 * d3 < 0.0f) ? 1 : 0;
        int sl3 = (d3 * d4 < 0.0f) ? 1 : 0;
        int cntLow = ((d0 * d1 < 0.0f) ? 1 : 0) + ((d1 * d2 < 0.0f) ? 1 : 0) + sl2 + sl3;
        int tm = __shfl_sync(FULL, sl2 + sl3, 31);   // bcorr[2c+1] = s126+s127

        // ---- high half: j = 256c + 128 + 4l + {0..3}; lane31: only 2 valid
        float e0 = v1.y - v1.x, e1 = v1.z - v1.y, e2 = v1.w - v1.z;
        float e3 = h1x - v1.w,  e4 = h1y - h1x;
        int cntHigh = ((e0 * e1 < 0.0f) ? 1 : 0) + ((e1 * e2 < 0.0f) ? 1 : 0);
        if (lane < 31)
            cntHigh += ((e2 * e3 < 0.0f) ? 1 : 0) + ((e3 * e4 < 0.0f) ? 1 : 0);

        int total = __reduce_add_sync(FULL, cntLow | (cntHigh << 16));
        if (lane == 2 * c) { segreg = total & 0xFFFF; bcreg = tm; }
        prevHigh = total >> 16;

        // lane 31 carries for next chunk's deferred boundary
        cx = v1.w;   // x[256c+255]
        cd = e2;     // d[256c+254]
    }
    // final high segment (m=31): s[4094], s[4095] invalid -> te = 0
    if (lane == 31) { segreg = prevHigh; bcreg = 0; }

    // ---- inclusive scan: sc at lane l = S[l+1]
    int sc = segreg;
    #pragma unroll
    for (int off = 1; off < 32; off <<= 1) {
        int n = __shfl_up_sync(FULL, sc, off);
        if (lane >= off) sc += n;
    }

    // ---- 57 outputs, 2 per lane
    const size_t obase = (size_t)row * N_WIN;
    #pragma unroll
    for (int half = 0; half < 2; half++) {
        int k  = lane + half * 32;
        int kk = (k < N_WIN) ? k : 0;
        int w, a; float L;
        if      (kk < 1)  { w = 4096; a = 0;             L = 3.612359948f; }
        else if (kk < 4)  { w = 2048; a = (kk - 1) * 8;  L = 3.311329954f; }
        else if (kk < 11) { w = 1024; a = (kk - 4) * 4;  L = 3.010299957f; }
        else if (kk < 26) { w = 512;  a = (kk - 11) * 2; L = 2.709269961f; }
        else              { w = 256;  a = kk - 26;       L = 2.408239965f; }
        int b = a + (w >> 7);

        int Sb = __shfl_sync(FULL, sc, b - 1);
        int Sa = __shfl_sync(FULL, sc, (a > 0) ? (a - 1) : 0);
        if (a == 0) Sa = 0;
        int bc = __shfl_sync(FULL, bcreg, b - 1);

        if (k < N_WIN) {
            float zc = (float)(Sb - Sa - bc);
            float wf = (float)w;
            float denom = L + log10f(wf / (wf + 0.4f * zc));
            out[obase + k] = L / denom;
        }
    }
}

extern "C" void kernel_launch(void* const* d_in, const int* in_sizes, int n_in,
                              void* d_out, int out_size) {
    const float* x = (const float*)d_in[0];
    float* out = (float*)d_out;
    int n_rows = in_sizes[0] / T_LEN;               // B*C = 4096
    int n_blocks = (n_rows + WARPS - 1) / WARPS;    // 512
    petrosian_kernel<<<n_blocks, 256>>>(x, out, n_rows);
}